// round 2
// baseline (speedup 1.0000x reference)
#include <cuda_runtime.h>
#include <cuda_bf16.h>

// DimIxLoss: reference epilogue is s -> exp(-s + min(s) - 0.1) where s is a
// scalar, and min(scalar)==scalar, so each term is exp(-0.1) exactly (IEEE:
// -a + a == 0 for all finite a). Output = 3 * exp(-0.1), independent of all
// inputs. Entire GEMM/softmax/top-k pipeline is dead code.
//
// fp32(exp(-0.1)) = 0x3F67A1C4 = 0.90483743f
// e + e + e in fp32 = 2.7145123f (0x402DBAA5); store the literal directly so
// the kernel body is MOV + STG + EXIT — no MUFU sequence at runtime.

__global__ void DimIxLoss_const_kernel(float* __restrict__ out) {
    out[0] = 2.7145123f;
}

extern "C" void kernel_launch(void* const* d_in, const int* in_sizes, int n_in,
                              void* d_out, int out_size) {
    (void)d_in; (void)in_sizes; (void)n_in; (void)out_size;
    DimIxLoss_const_kernel<<<1, 1>>>((float*)d_out);
}

// round 3
// speedup vs baseline: 1.0556x; 1.0556x over previous
#include <cuda_runtime.h>
#include <cuda_bf16.h>

// DimIxLoss: reference epilogue is s -> exp(-s + min(s) - 0.1) with scalar s,
// and min(scalar)==scalar, so each term is exp(-0.1) exactly (IEEE: -a+a==0
// for finite a). Output = 3*exp(-0.1) = 2.7145123f (0x402DBAA5), independent
// of all inputs — verified bit-exact (rel_err 0.0) in R2.
//
// R3: replace the kernel node with a 4-byte D2D memcpy node from a statically
// initialized __device__ constant. Explicitly allowed by harness rules
// ("cudaMemcpyAsync device-to-device ... are fine"); avoids grid dispatch
// entirely on each graph replay.

__device__ float g_dimix_const = 2.7145123f;  // == fp32(exp(-0.1f))*3, e+e+e

extern "C" void kernel_launch(void* const* d_in, const int* in_sizes, int n_in,
                              void* d_out, int out_size) {
    (void)d_in; (void)in_sizes; (void)n_in; (void)out_size;
    void* src = nullptr;
    cudaGetSymbolAddress(&src, g_dimix_const);  // immediate API, capture-safe
    cudaMemcpyAsync(d_out, src, sizeof(float), cudaMemcpyDeviceToDevice, 0);
}

// round 5
// speedup vs baseline: 1.5050x; 1.4257x over previous
#include <cuda_runtime.h>
#include <cuda_bf16.h>

// DimIxLoss: reference epilogue is s -> exp(-s + min(s) - 0.1) with scalar s,
// and min(scalar)==scalar, so each term is exp(-0.1) exactly (IEEE: -a+a==0
// for finite a). Output = 3*exp(-0.1) = 2.7145123f (bits 0x402DBAA5),
// independent of all inputs — verified bit-exact (rel_err 0.0) in R2/R3.
//
// R5: R4 retry with CUDA-13 graph-capture API signatures (edgeData params).
// During capture, insert a 4-byte MEMSET node (immediate pattern, no source
// read) instead of the memcpy node. Outside capture, fall back to the proven
// D2D memcpy from a __device__ constant — byte-identical output either way.

__device__ float g_dimix_const = 2.7145123f;  // fp32(exp(-0.1f)) summed 3x

extern "C" void kernel_launch(void* const* d_in, const int* in_sizes, int n_in,
                              void* d_out, int out_size) {
    (void)d_in; (void)in_sizes; (void)n_in; (void)out_size;

    cudaStream_t stream = 0;
    cudaStreamCaptureStatus cap = cudaStreamCaptureStatusNone;
    unsigned long long cap_id = 0;
    cudaGraph_t graph = nullptr;
    const cudaGraphNode_t* deps = nullptr;
    const cudaGraphEdgeData* edge = nullptr;
    size_t n_deps = 0;

    cudaError_t qerr = cudaStreamGetCaptureInfo(stream, &cap, &cap_id,
                                                &graph, &deps, &edge, &n_deps);

    if (qerr == cudaSuccess && cap == cudaStreamCaptureStatusActive && graph) {
        cudaMemsetParams p = {};
        p.dst = d_out;
        p.value = 0x402DBAA5u;   // bit pattern of 2.7145123f
        p.elementSize = 4;
        p.width = 1;
        p.height = 1;
        p.pitch = 0;
        cudaGraphNode_t node = nullptr;
        if (cudaGraphAddMemsetNode(&node, graph, deps, n_deps, &p) == cudaSuccess) {
            cudaStreamUpdateCaptureDependencies(stream, &node, /*edgeData=*/nullptr,
                                                1, cudaStreamSetCaptureDependencies);
            return;
        }
        // fall through to memcpy if node insertion failed (still capturable)
    }

    // Non-capture (correctness) path, or fallback: proven R3 D2D copy.
    void* src = nullptr;
    cudaGetSymbolAddress(&src, g_dimix_const);
    cudaMemcpyAsync(d_out, src, sizeof(float), cudaMemcpyDeviceToDevice, stream);
}